// round 4
// baseline (speedup 1.0000x reference)
#include <cuda_runtime.h>
#include <cstdint>

// CrossMerge3D: out[b,c,i,j,k] = ( sum of 12 scans in 3 orientations ) / 12
//   family i (s=0..3):  n = i*1024 + j*32 + k   (fwd s0,s1; flipped s2,s3)
//   family j (s=4..7):  n = j*1024 + k*32 + i
//   family k (s=8..11): n = k*1024 + i*32 + j
//
// Block = (b, c, i-slab of 8). All GMEM traffic is linear in each family's
// native layout (float4, incl. reversed-contiguous for flipped scans);
// permutation handled in a bank-conflict-free padded smem accumulator.
// launch_bounds(256,6): 6 blocks/SM -> the whole 768-block grid is one wave
// (888 slots), eliminating the 28-block straggler tail seen at 5 blocks/SM.

#define DD      32
#define NVOL    32768            // 32^3
#define CCH     96
#define CN      (CCH * NVOL)     // 3145728
#define SLAB_I  8
#define SLAB_N  (SLAB_I * DD * DD)   // 8192
#define THREADS 256
#define CHUNKS  (SLAB_N / 4)     // 2048 float4-chunks per phase
#define ITERS   (CHUNKS / THREADS)   // 8

// padded smem index: injective (per-ii span 0..1054 < 1060),
// bank(f) = (4*ii + j + k) mod 32  (1060 mod 32 = 4, 33 mod 32 = 1)
#define STRIDE_II 1060
__device__ __forceinline__ int fidx(int ii, int j, int k) {
    return ii * STRIDE_II + j * 33 + k;
}

__global__ __launch_bounds__(THREADS, 6)
void cross_merge3d_kernel(const float* __restrict__ ys, float* __restrict__ out) {
    __shared__ float acc[7 * STRIDE_II + 31 * 33 + 31 + 2];   // 8476 floats

    const int bid = blockIdx.x;
    const int a   = bid & 3;               // i-slab
    const int c   = (bid >> 2) % CCH;
    const int b   = bid / (4 * CCH);
    const int tid = threadIdx.x;

    const float* base = ys + (size_t)b * (12 * (size_t)CN) + (size_t)c * NVOL;

    // ---------------- Phase A: family i (s = 0..3), init accumulator ----------------
    {
        const float* q0 = base + 0 * (size_t)CN;
        const float* q1 = base + 1 * (size_t)CN;
        const float* q2 = base + 2 * (size_t)CN;
        const float* q3 = base + 3 * (size_t)CN;
        #pragma unroll
        for (int it = 0; it < ITERS; it++) {
            int chunk   = it * THREADS + tid;
            int n_local = chunk * 4;
            int ii = n_local >> 10;
            int j  = (n_local >> 5) & 31;
            int k  = n_local & 31;
            int n_g = a * SLAB_N + n_local;
            float4 f0 = *(const float4*)(q0 + n_g);
            float4 f1 = *(const float4*)(q1 + n_g);
            int r_g = NVOL - 4 - n_g;
            float4 r2 = *(const float4*)(q2 + r_g);
            float4 r3 = *(const float4*)(q3 + r_g);
            int f = fidx(ii, j, k);
            acc[f + 0] = f0.x + f1.x + r2.w + r3.w;
            acc[f + 1] = f0.y + f1.y + r2.z + r3.z;
            acc[f + 2] = f0.z + f1.z + r2.y + r3.y;
            acc[f + 3] = f0.w + f1.w + r2.x + r3.x;
        }
    }
    __syncthreads();

    // ---------------- Phase B: family j (s = 4..7), n = j*1024 + k*32 + i ----------------
    {
        const float* q4 = base + 4 * (size_t)CN;
        const float* q5 = base + 5 * (size_t)CN;
        const float* q6 = base + 6 * (size_t)CN;
        const float* q7 = base + 7 * (size_t)CN;
        #pragma unroll
        for (int it = 0; it < ITERS; it++) {
            int chunk = it * THREADS + tid;
            int t4 = chunk & 1;                 // i-subchunk (i = 8a + 4*t4 + e)
            int k  = (chunk >> 1) & 31;
            int j  = chunk >> 6;
            int m  = j * 1024 + k * 32 + a * SLAB_I + 4 * t4;
            float4 f4 = *(const float4*)(q4 + m);
            float4 f5 = *(const float4*)(q5 + m);
            int r_m = NVOL - 4 - m;
            float4 r6 = *(const float4*)(q6 + r_m);
            float4 r7 = *(const float4*)(q7 + r_m);
            int iib = 4 * t4;
            acc[fidx(iib + 0, j, k)] += f4.x + f5.x + r6.w + r7.w;
            acc[fidx(iib + 1, j, k)] += f4.y + f5.y + r6.z + r7.z;
            acc[fidx(iib + 2, j, k)] += f4.z + f5.z + r6.y + r7.y;
            acc[fidx(iib + 3, j, k)] += f4.w + f5.w + r6.x + r7.x;
        }
    }
    __syncthreads();

    // ---------------- Phase C: family k (s = 8..11), n = k*1024 + i*32 + j ----------------
    {
        const float* q8  = base + 8  * (size_t)CN;
        const float* q9  = base + 9  * (size_t)CN;
        const float* q10 = base + 10 * (size_t)CN;
        const float* q11 = base + 11 * (size_t)CN;
        #pragma unroll
        for (int it = 0; it < ITERS; it++) {
            int chunk = it * THREADS + tid;
            int j4 = chunk & 7;                 // j = 4*j4 + e
            int k  = (chunk >> 3) & 31;
            int ii = chunk >> 8;
            int m  = k * 1024 + (a * SLAB_I + ii) * 32 + 4 * j4;
            float4 f8 = *(const float4*)(q8  + m);
            float4 f9 = *(const float4*)(q9  + m);
            int r_m = NVOL - 4 - m;
            float4 rA = *(const float4*)(q10 + r_m);
            float4 rB = *(const float4*)(q11 + r_m);
            int jb = 4 * j4;
            acc[fidx(ii, jb + 0, k)] += f8.x + f9.x + rA.w + rB.w;
            acc[fidx(ii, jb + 1, k)] += f8.y + f9.y + rA.z + rB.z;
            acc[fidx(ii, jb + 2, k)] += f8.z + f9.z + rA.y + rB.y;
            acc[fidx(ii, jb + 3, k)] += f8.w + f9.w + rA.x + rB.x;
        }
    }
    __syncthreads();

    // ---------------- Phase D: scale + coalesced store ----------------
    {
        float* ob = out + ((size_t)b * CCH + c) * NVOL + a * SLAB_N;
        const float s = 1.0f / 12.0f;
        #pragma unroll
        for (int it = 0; it < ITERS; it++) {
            int chunk   = it * THREADS + tid;
            int n_local = chunk * 4;
            int ii = n_local >> 10;
            int j  = (n_local >> 5) & 31;
            int k  = n_local & 31;
            int f = fidx(ii, j, k);
            float4 o;
            o.x = acc[f + 0] * s;
            o.y = acc[f + 1] * s;
            o.z = acc[f + 2] * s;
            o.w = acc[f + 3] * s;
            *(float4*)(ob + n_local) = o;
        }
    }
}

extern "C" void kernel_launch(void* const* d_in, const int* in_sizes, int n_in,
                              void* d_out, int out_size) {
    const float* ys = (const float*)d_in[0];
    float* out = (float*)d_out;
    // grid = B * C * slabs = 2 * 96 * 4 = 768
    cross_merge3d_kernel<<<768, THREADS>>>(ys, out);
}

// round 5
// speedup vs baseline: 1.2470x; 1.2470x over previous
#include <cuda_runtime.h>
#include <cstdint>

// CrossMerge3D: out[b,c,i,j,k] = ( sum of 12 scans in 3 orientations ) / 12
//   family i (s=0..3):  n = i*1024 + j*32 + k   (fwd s0,s1; flipped s2,s3)
//   family j (s=4..7):  n = j*1024 + k*32 + i
//   family k (s=8..11): n = k*1024 + i*32 + j
//
// Block = (b, c, i-slab of 4), 128 threads, 10 blocks/SM -> grid of 1536
// blocks = ~1.04 waves with a tail of 56 quarter-size blocks (~1 small-block
// duration) instead of the 28 full-size-block tail that capped R2 at 62% DRAM.
// All GMEM traffic is float4-coalesced in each family's native layout;
// permutation via a bank-conflict-free padded smem accumulator.

#define DD      32
#define NVOL    32768            // 32^3
#define CCH     96
#define CN      (CCH * NVOL)     // 3145728
#define SLAB_I  4
#define NSLAB   (DD / SLAB_I)    // 8
#define SLAB_N  (SLAB_I * DD * DD)   // 4096
#define THREADS 128
#define CHUNKS  (SLAB_N / 4)     // 1024 float4-chunks per phase
#define ITERS   (CHUNKS / THREADS)   // 8

// padded smem index: injective (per-ii span 0..1054 < 1060),
// bank(f) = (4*ii + j + k) mod 32  (1060 mod 32 = 4, 33 mod 32 = 1)
#define STRIDE_II 1060
__device__ __forceinline__ int fidx(int ii, int j, int k) {
    return ii * STRIDE_II + j * 33 + k;
}

__global__ __launch_bounds__(THREADS, 10)
void cross_merge3d_kernel(const float* __restrict__ ys, float* __restrict__ out) {
    __shared__ float acc[3 * STRIDE_II + 31 * 33 + 31 + 2];   // 4237 floats (~17KB)

    const int bid = blockIdx.x;
    const int a   = bid & (NSLAB - 1);        // i-slab (0..7)
    const int c   = (bid >> 3) % CCH;
    const int b   = bid / (NSLAB * CCH);
    const int tid = threadIdx.x;

    const float* base = ys + (size_t)b * (12 * (size_t)CN) + (size_t)c * NVOL;

    // ---------------- Phase A: family i (s = 0..3), init accumulator ----------------
    {
        const float* q0 = base + 0 * (size_t)CN;
        const float* q1 = base + 1 * (size_t)CN;
        const float* q2 = base + 2 * (size_t)CN;
        const float* q3 = base + 3 * (size_t)CN;
        #pragma unroll
        for (int it = 0; it < ITERS; it++) {
            int chunk   = it * THREADS + tid;
            int n_local = chunk * 4;
            int ii = n_local >> 10;               // 0..3
            int j  = (n_local >> 5) & 31;
            int k  = n_local & 31;
            int n_g = a * SLAB_N + n_local;
            float4 f0 = *(const float4*)(q0 + n_g);
            float4 f1 = *(const float4*)(q1 + n_g);
            int r_g = NVOL - 4 - n_g;
            float4 r2 = *(const float4*)(q2 + r_g);
            float4 r3 = *(const float4*)(q3 + r_g);
            int f = fidx(ii, j, k);
            acc[f + 0] = f0.x + f1.x + r2.w + r3.w;
            acc[f + 1] = f0.y + f1.y + r2.z + r3.z;
            acc[f + 2] = f0.z + f1.z + r2.y + r3.y;
            acc[f + 3] = f0.w + f1.w + r2.x + r3.x;
        }
    }
    __syncthreads();

    // ---------------- Phase B: family j (s = 4..7), n = j*1024 + k*32 + i ----------------
    // One float4 i-chunk per (j,k): i = 4a .. 4a+3
    {
        const float* q4 = base + 4 * (size_t)CN;
        const float* q5 = base + 5 * (size_t)CN;
        const float* q6 = base + 6 * (size_t)CN;
        const float* q7 = base + 7 * (size_t)CN;
        #pragma unroll
        for (int it = 0; it < ITERS; it++) {
            int chunk = it * THREADS + tid;
            int k  = chunk & 31;
            int j  = chunk >> 5;
            int m  = j * 1024 + k * 32 + a * SLAB_I;
            float4 f4 = *(const float4*)(q4 + m);
            float4 f5 = *(const float4*)(q5 + m);
            int r_m = NVOL - 4 - m;
            float4 r6 = *(const float4*)(q6 + r_m);
            float4 r7 = *(const float4*)(q7 + r_m);
            acc[fidx(0, j, k)] += f4.x + f5.x + r6.w + r7.w;
            acc[fidx(1, j, k)] += f4.y + f5.y + r6.z + r7.z;
            acc[fidx(2, j, k)] += f4.z + f5.z + r6.y + r7.y;
            acc[fidx(3, j, k)] += f4.w + f5.w + r6.x + r7.x;
        }
    }
    __syncthreads();

    // ---------------- Phase C: family k (s = 8..11), n = k*1024 + i*32 + j ----------------
    {
        const float* q8  = base + 8  * (size_t)CN;
        const float* q9  = base + 9  * (size_t)CN;
        const float* q10 = base + 10 * (size_t)CN;
        const float* q11 = base + 11 * (size_t)CN;
        #pragma unroll
        for (int it = 0; it < ITERS; it++) {
            int chunk = it * THREADS + tid;
            int j4 = chunk & 7;                 // j = 4*j4 + e
            int k  = (chunk >> 3) & 31;
            int ii = chunk >> 8;                // 0..3
            int m  = k * 1024 + (a * SLAB_I + ii) * 32 + 4 * j4;
            float4 f8 = *(const float4*)(q8  + m);
            float4 f9 = *(const float4*)(q9  + m);
            int r_m = NVOL - 4 - m;
            float4 rA = *(const float4*)(q10 + r_m);
            float4 rB = *(const float4*)(q11 + r_m);
            int jb = 4 * j4;
            acc[fidx(ii, jb + 0, k)] += f8.x + f9.x + rA.w + rB.w;
            acc[fidx(ii, jb + 1, k)] += f8.y + f9.y + rA.z + rB.z;
            acc[fidx(ii, jb + 2, k)] += f8.z + f9.z + rA.y + rB.y;
            acc[fidx(ii, jb + 3, k)] += f8.w + f9.w + rA.x + rB.x;
        }
    }
    __syncthreads();

    // ---------------- Phase D: scale + coalesced store ----------------
    {
        float* ob = out + ((size_t)b * CCH + c) * NVOL + a * SLAB_N;
        const float s = 1.0f / 12.0f;
        #pragma unroll
        for (int it = 0; it < ITERS; it++) {
            int chunk   = it * THREADS + tid;
            int n_local = chunk * 4;
            int ii = n_local >> 10;
            int j  = (n_local >> 5) & 31;
            int k  = n_local & 31;
            int f = fidx(ii, j, k);
            float4 o;
            o.x = acc[f + 0] * s;
            o.y = acc[f + 1] * s;
            o.z = acc[f + 2] * s;
            o.w = acc[f + 3] * s;
            *(float4*)(ob + n_local) = o;
        }
    }
}

extern "C" void kernel_launch(void* const* d_in, const int* in_sizes, int n_in,
                              void* d_out, int out_size) {
    const float* ys = (const float*)d_in[0];
    float* out = (float*)d_out;
    // grid = B * C * slabs = 2 * 96 * 8 = 1536
    cross_merge3d_kernel<<<1536, THREADS>>>(ys, out);
}

// round 6
// speedup vs baseline: 1.5081x; 1.2094x over previous
#include <cuda_runtime.h>
#include <cstdint>

// CrossMerge3D: out[b,c,i,j,k] = ( sum of 12 scans in 3 orientations ) / 12
//   family i (s=0..3):  n = i*1024 + j*32 + k   (fwd s0,s1; flipped s2,s3)
//   family j (s=4..7):  n = j*1024 + k*32 + i
//   family k (s=8..11): n = k*1024 + i*32 + j
//
// Block = (b, c, i-slab of 4) with 256 threads (same per-warp load shape as
// the best 66us variant, half the work per block -> half the ramp-down tail).
// All GMEM traffic is float4-coalesced in each family's native layout;
// permutation via a bank-conflict-free padded smem accumulator.
// Output uses streaming stores (write-once data, don't pollute L2).

#define DD      32
#define NVOL    32768            // 32^3
#define CCH     96
#define CN      (CCH * NVOL)     // 3145728
#define SLAB_I  4
#define NSLAB   (DD / SLAB_I)    // 8
#define SLAB_N  (SLAB_I * DD * DD)   // 4096
#define THREADS 256
#define CHUNKS  (SLAB_N / 4)     // 1024 float4-chunks per phase
#define ITERS   (CHUNKS / THREADS)   // 4

// padded smem index: injective (per-ii span 0..1054 < 1060),
// bank(f) = (4*ii + j + k) mod 32  (1060 mod 32 = 4, 33 mod 32 = 1)
#define STRIDE_II 1060
__device__ __forceinline__ int fidx(int ii, int j, int k) {
    return ii * STRIDE_II + j * 33 + k;
}

__global__ __launch_bounds__(THREADS)
void cross_merge3d_kernel(const float* __restrict__ ys, float* __restrict__ out) {
    __shared__ float acc[3 * STRIDE_II + 31 * 33 + 31 + 2];   // 4236 floats (~17KB)

    const int bid = blockIdx.x;
    const int a   = bid & (NSLAB - 1);        // i-slab (0..7)
    const int c   = (bid >> 3) % CCH;
    const int b   = bid / (NSLAB * CCH);
    const int tid = threadIdx.x;

    const float* base = ys + (size_t)b * (12 * (size_t)CN) + (size_t)c * NVOL;

    // ---------------- Phase A: family i (s = 0..3), init accumulator ----------------
    {
        const float* q0 = base + 0 * (size_t)CN;
        const float* q1 = base + 1 * (size_t)CN;
        const float* q2 = base + 2 * (size_t)CN;
        const float* q3 = base + 3 * (size_t)CN;
        #pragma unroll
        for (int it = 0; it < ITERS; it++) {
            int chunk   = it * THREADS + tid;
            int n_local = chunk * 4;
            int ii = n_local >> 10;               // 0..3
            int j  = (n_local >> 5) & 31;
            int k  = n_local & 31;
            int n_g = a * SLAB_N + n_local;
            float4 f0 = *(const float4*)(q0 + n_g);
            float4 f1 = *(const float4*)(q1 + n_g);
            int r_g = NVOL - 4 - n_g;
            float4 r2 = *(const float4*)(q2 + r_g);
            float4 r3 = *(const float4*)(q3 + r_g);
            int f = fidx(ii, j, k);
            acc[f + 0] = f0.x + f1.x + r2.w + r3.w;
            acc[f + 1] = f0.y + f1.y + r2.z + r3.z;
            acc[f + 2] = f0.z + f1.z + r2.y + r3.y;
            acc[f + 3] = f0.w + f1.w + r2.x + r3.x;
        }
    }
    __syncthreads();

    // ---------------- Phase B: family j (s = 4..7), n = j*1024 + k*32 + i ----------------
    // One float4 i-chunk per (j,k): i = 4a .. 4a+3
    {
        const float* q4 = base + 4 * (size_t)CN;
        const float* q5 = base + 5 * (size_t)CN;
        const float* q6 = base + 6 * (size_t)CN;
        const float* q7 = base + 7 * (size_t)CN;
        #pragma unroll
        for (int it = 0; it < ITERS; it++) {
            int chunk = it * THREADS + tid;
            int k  = chunk & 31;
            int j  = chunk >> 5;
            int m  = j * 1024 + k * 32 + a * SLAB_I;
            float4 f4 = *(const float4*)(q4 + m);
            float4 f5 = *(const float4*)(q5 + m);
            int r_m = NVOL - 4 - m;
            float4 r6 = *(const float4*)(q6 + r_m);
            float4 r7 = *(const float4*)(q7 + r_m);
            acc[fidx(0, j, k)] += f4.x + f5.x + r6.w + r7.w;
            acc[fidx(1, j, k)] += f4.y + f5.y + r6.z + r7.z;
            acc[fidx(2, j, k)] += f4.z + f5.z + r6.y + r7.y;
            acc[fidx(3, j, k)] += f4.w + f5.w + r6.x + r7.x;
        }
    }
    __syncthreads();

    // ---------------- Phase C: family k (s = 8..11), n = k*1024 + i*32 + j ----------------
    {
        const float* q8  = base + 8  * (size_t)CN;
        const float* q9  = base + 9  * (size_t)CN;
        const float* q10 = base + 10 * (size_t)CN;
        const float* q11 = base + 11 * (size_t)CN;
        #pragma unroll
        for (int it = 0; it < ITERS; it++) {
            int chunk = it * THREADS + tid;
            int j4 = chunk & 7;                 // j = 4*j4 + e
            int k  = (chunk >> 3) & 31;
            int ii = chunk >> 8;                // 0..3
            int m  = k * 1024 + (a * SLAB_I + ii) * 32 + 4 * j4;
            float4 f8 = *(const float4*)(q8  + m);
            float4 f9 = *(const float4*)(q9  + m);
            int r_m = NVOL - 4 - m;
            float4 rA = *(const float4*)(q10 + r_m);
            float4 rB = *(const float4*)(q11 + r_m);
            int jb = 4 * j4;
            acc[fidx(ii, jb + 0, k)] += f8.x + f9.x + rA.w + rB.w;
            acc[fidx(ii, jb + 1, k)] += f8.y + f9.y + rA.z + rB.z;
            acc[fidx(ii, jb + 2, k)] += f8.z + f9.z + rA.y + rB.y;
            acc[fidx(ii, jb + 3, k)] += f8.w + f9.w + rA.x + rB.x;
        }
    }
    __syncthreads();

    // ---------------- Phase D: scale + coalesced streaming store ----------------
    {
        float* ob = out + ((size_t)b * CCH + c) * NVOL + a * SLAB_N;
        const float s = 1.0f / 12.0f;
        #pragma unroll
        for (int it = 0; it < ITERS; it++) {
            int chunk   = it * THREADS + tid;
            int n_local = chunk * 4;
            int ii = n_local >> 10;
            int j  = (n_local >> 5) & 31;
            int k  = n_local & 31;
            int f = fidx(ii, j, k);
            float4 o;
            o.x = acc[f + 0] * s;
            o.y = acc[f + 1] * s;
            o.z = acc[f + 2] * s;
            o.w = acc[f + 3] * s;
            __stcs((float4*)(ob + n_local), o);
        }
    }
}

extern "C" void kernel_launch(void* const* d_in, const int* in_sizes, int n_in,
                              void* d_out, int out_size) {
    const float* ys = (const float*)d_in[0];
    float* out = (float*)d_out;
    // grid = B * C * slabs = 2 * 96 * 8 = 1536
    cross_merge3d_kernel<<<1536, THREADS>>>(ys, out);
}